// round 1
// baseline (speedup 1.0000x reference)
#include <cuda_runtime.h>
#include <math.h>

// ---------------- problem constants ----------------
#define Bb 2
#define Tt 2048
#define Dd 2560
#define Hh 8
#define Gg 4
#define HD 256
#define NQ (Hh*HD)     // 2048
#define NKV (Gg*HD)    // 1024
#define MROWS (Bb*Tt)  // 4096
#define QK_SCALE 0.0625f
#define WINDOW 1024

// ---------------- scratch (static device globals; no allocation) -----------
__device__ float g_q[(size_t)MROWS * NQ];
__device__ float g_k[(size_t)MROWS * NKV];
__device__ float g_v[(size_t)MROWS * NKV];
__device__ float g_ao[(size_t)MROWS * NQ];

// ---------------- SGEMM: C[M,N] = A[M,K] * B[K,N], all row-major ----------
// Requires: M % 128 == 0, N % 128 == 0, K % 16 == 0 (true for all our shapes)
#define BM 128
#define BN 128
#define BK 16
#define TM 8
#define TN 8

__global__ __launch_bounds__(256) void sgemm_kernel(
    const float* __restrict__ A, const float* __restrict__ B,
    float* __restrict__ C, int M, int N, int K)
{
    __shared__ float As[BK][BM + 4];
    __shared__ float Bs[BK][BN + 4];

    int tid = threadIdx.x;
    int tx = tid & 15;
    int ty = tid >> 4;
    int row0 = blockIdx.y * BM;
    int col0 = blockIdx.x * BN;

    float acc[TM][TN];
#pragma unroll
    for (int i = 0; i < TM; i++)
#pragma unroll
        for (int j = 0; j < TN; j++) acc[i][j] = 0.f;

    for (int kt = 0; kt < K; kt += BK) {
        // load A tile [BM x BK], store transposed As[k][m]
#pragma unroll
        for (int it = 0; it < 2; it++) {
            int s = tid + it * 256;      // 512 float4 slots
            int m = s >> 2;              // 4 float4 per 16-float row
            int kq = (s & 3) << 2;
            float4 v = *(const float4*)(A + (size_t)(row0 + m) * K + kt + kq);
            As[kq + 0][m] = v.x;
            As[kq + 1][m] = v.y;
            As[kq + 2][m] = v.z;
            As[kq + 3][m] = v.w;
        }
        // load B tile [BK x BN]
#pragma unroll
        for (int it = 0; it < 2; it++) {
            int s = tid + it * 256;
            int k = s >> 5;              // 32 float4 per 128-float row
            int n = (s & 31) << 2;
            *(float4*)(&Bs[k][n]) = *(const float4*)(B + (size_t)(kt + k) * N + col0 + n);
        }
        __syncthreads();

#pragma unroll
        for (int k = 0; k < BK; k++) {
            float a[TM], bb[TN];
#pragma unroll
            for (int i = 0; i < TM; i++) a[i] = As[k][ty * TM + i];
#pragma unroll
            for (int j = 0; j < TN; j++) bb[j] = Bs[k][tx * TN + j];
#pragma unroll
            for (int i = 0; i < TM; i++)
#pragma unroll
                for (int j = 0; j < TN; j++)
                    acc[i][j] += a[i] * bb[j];
        }
        __syncthreads();
    }

#pragma unroll
    for (int i = 0; i < TM; i++) {
        float* cp = C + (size_t)(row0 + ty * TM + i) * N + col0 + tx * TN;
#pragma unroll
        for (int j = 0; j < TN; j += 4) {
            float4 v = make_float4(acc[i][j], acc[i][j + 1], acc[i][j + 2], acc[i][j + 3]);
            *(float4*)(cp + j) = v;
        }
    }
}

// ---------------- Gemma RMSNorm over contiguous 256-float rows -------------
__global__ __launch_bounds__(256) void rmsnorm_kernel(
    float* __restrict__ buf, const float* __restrict__ scale)
{
    int row = blockIdx.x;
    int d = threadIdx.x;
    float* p = buf + (size_t)row * HD;
    float x = p[d];
    float v = x * x;
#pragma unroll
    for (int o = 16; o > 0; o >>= 1) v += __shfl_xor_sync(0xffffffffu, v, o);
    __shared__ float ws[8];
    __shared__ float stot;
    if ((d & 31) == 0) ws[d >> 5] = v;
    __syncthreads();
    if (d == 0) {
        float s = 0.f;
#pragma unroll
        for (int i = 0; i < 8; i++) s += ws[i];
        stot = s;
    }
    __syncthreads();
    float r = rsqrtf(stot * (1.f / HD) + 1e-6f);
    p[d] = x * r * (1.f + scale[d]);
}

// ---------------- sliding-window flash attention (fp32) --------------------
// One block = 32 queries of one (b, h). 256 threads.
// kv head = h % 4 (faithful to the reference's reshape quirk).
#define AQT 32
#define QPAD 257   // 256 + 1: breaks stride-256 bank conflicts
#define SPAD 33

__global__ __launch_bounds__(256) void attn_kernel()
{
    extern __shared__ float sm[];
    float* Qs = sm;                   // [32][257]
    float* Ks = Qs + AQT * QPAD;      // [32][257]
    float* Vs = Ks + AQT * QPAD;      // [32][257]
    float* Ss = Vs + AQT * QPAD;      // [32][33]
    float* lrow = Ss + AQT * SPAD;    // [32]
    float* arow = lrow + AQT;         // [32]

    int tid = threadIdx.x;
    int qt = blockIdx.x;   // query tile
    int h  = blockIdx.y;
    int b  = blockIdx.z;
    int t0 = qt * AQT;
    int kvh = h & (Gg - 1);

    // Q tile (scale folded in)
    for (int idx = tid; idx < AQT * HD; idx += 256) {
        int qi = idx >> 8, d = idx & 255;
        Qs[qi * QPAD + d] =
            g_q[((size_t)(b * Tt + t0 + qi)) * NQ + h * HD + d] * QK_SCALE;
    }

    int qi_o = tid >> 3;   // output query row (4 per warp)
    int dseg = tid & 7;    // output dim lane: handles d = dseg + 8*j
    float o[32];
#pragma unroll
    for (int j = 0; j < 32; j++) o[j] = 0.f;

    float mreg = -1e30f, lreg = 0.f;   // live only in tid < 32

    int kb0 = max(0, t0 - (WINDOW - 1)) >> 5;
    int kb1 = (t0 + AQT - 1) >> 5;

    for (int kb = kb0; kb <= kb1; kb++) {
        int s0 = kb * AQT;
        __syncthreads();  // previous PV done before overwriting K/V/S

        for (int idx = tid; idx < AQT * HD; idx += 256) {
            int ki = idx >> 8, d = idx & 255;
            size_t gr = ((size_t)(b * Tt + s0 + ki)) * NKV + kvh * HD + d;
            Ks[ki * QPAD + d] = g_k[gr];
            Vs[ki * QPAD + d] = g_v[gr];
        }
        __syncthreads();

        // scores: 2x2 micro-tile per thread
        int q2 = (tid >> 4) << 1;
        int k2 = (tid & 15) << 1;
        float s00 = 0.f, s01 = 0.f, s10 = 0.f, s11 = 0.f;
        const float* q0p = Qs + q2 * QPAD;
        const float* q1p = q0p + QPAD;
        const float* k0p = Ks + k2 * QPAD;
        const float* k1p = k0p + QPAD;
#pragma unroll 4
        for (int d = 0; d < HD; d++) {
            float q0v = q0p[d], q1v = q1p[d];
            float k0v = k0p[d], k1v = k1p[d];
            s00 += q0v * k0v; s01 += q0v * k1v;
            s10 += q1v * k0v; s11 += q1v * k1v;
        }
        {
            int tq0 = t0 + q2, tq1 = tq0 + 1;
            int kk0 = s0 + k2, kk1 = kk0 + 1;
            Ss[q2 * SPAD + k2]           = (kk0 > tq0 || kk0 < tq0 - (WINDOW - 1)) ? -1e30f : s00;
            Ss[q2 * SPAD + k2 + 1]       = (kk1 > tq0 || kk1 < tq0 - (WINDOW - 1)) ? -1e30f : s01;
            Ss[(q2 + 1) * SPAD + k2]     = (kk0 > tq1 || kk0 < tq1 - (WINDOW - 1)) ? -1e30f : s10;
            Ss[(q2 + 1) * SPAD + k2 + 1] = (kk1 > tq1 || kk1 < tq1 - (WINDOW - 1)) ? -1e30f : s11;
        }
        __syncthreads();

        // online softmax (one thread per query row)
        if (tid < 32) {
            float* srow = Ss + tid * SPAD;
            float mnew = mreg;
#pragma unroll
            for (int j = 0; j < 32; j++) mnew = fmaxf(mnew, srow[j]);
            float alpha = __expf(mreg - mnew);
            float sum = 0.f;
#pragma unroll
            for (int j = 0; j < 32; j++) {
                float s = srow[j];
                float p = __expf(s - mnew);
                if (s < -1e29f) p = 0.f;   // guards fully-masked rows (m stuck at -1e30)
                srow[j] = p;
                sum += p;
            }
            lreg = lreg * alpha + sum;
            mreg = mnew;
            arow[tid] = alpha;
            lrow[tid] = lreg;
        }
        __syncthreads();

        // O = O*alpha + P @ V
        float al = arow[qi_o];
#pragma unroll
        for (int j = 0; j < 32; j++) o[j] *= al;
        const float* prow = Ss + qi_o * SPAD;
#pragma unroll 8
        for (int k = 0; k < 32; k++) {
            float p = prow[k];
            const float* vrow = Vs + k * QPAD + dseg;
#pragma unroll
            for (int j = 0; j < 32; j++) o[j] += p * vrow[j * 8];
        }
    }
    __syncthreads();

    float invl = 1.f / lrow[qi_o];
    float* op = g_ao + ((size_t)(b * Tt + t0 + qi_o)) * NQ + h * HD + dseg;
#pragma unroll
    for (int j = 0; j < 32; j++) op[j * 8] = o[j] * invl;
}

// ---------------- launch ----------------------------------------------------
extern "C" void kernel_launch(void* const* d_in, const int* in_sizes, int n_in,
                              void* d_out, int out_size)
{
    const float* x   = (const float*)d_in[0];
    const float* Wq  = (const float*)d_in[1];
    const float* Wk  = (const float*)d_in[2];
    const float* Wv  = (const float*)d_in[3];
    const float* Wo  = (const float*)d_in[4];
    const float* qsc = (const float*)d_in[5];
    const float* ksc = (const float*)d_in[6];
    float* out = (float*)d_out;

    void *pq, *pk, *pv, *pao;
    cudaGetSymbolAddress(&pq,  g_q);
    cudaGetSymbolAddress(&pk,  g_k);
    cudaGetSymbolAddress(&pv,  g_v);
    cudaGetSymbolAddress(&pao, g_ao);
    float* dq  = (float*)pq;
    float* dk  = (float*)pk;
    float* dv  = (float*)pv;
    float* dao = (float*)pao;

    // projections
    {
        dim3 blk(256);
        dim3 gq(NQ / BN,  MROWS / BM);
        dim3 gk(NKV / BN, MROWS / BM);
        sgemm_kernel<<<gq, blk>>>(x, Wq, dq, MROWS, NQ,  Dd);
        sgemm_kernel<<<gk, blk>>>(x, Wk, dk, MROWS, NKV, Dd);
        sgemm_kernel<<<gk, blk>>>(x, Wv, dv, MROWS, NKV, Dd);
    }

    // qk-norm (rows of 256 contiguous floats)
    rmsnorm_kernel<<<MROWS * Hh, 256>>>(dq, qsc);
    rmsnorm_kernel<<<MROWS * Gg, 256>>>(dk, ksc);

    // attention
    {
        size_t smem = (size_t)(3 * AQT * QPAD + AQT * SPAD + 2 * AQT) * sizeof(float);
        cudaFuncSetAttribute(attn_kernel,
                             cudaFuncAttributeMaxDynamicSharedMemorySize, (int)smem);
        dim3 grid(Tt / AQT, Hh, Bb);
        attn_kernel<<<grid, 256, smem>>>();
    }

    // output projection
    {
        dim3 blk(256);
        dim3 go(Dd / BN, MROWS / BM);
        sgemm_kernel<<<go, blk>>>(dao, Wo, out, MROWS, Dd, NQ);
    }
}

// round 3
// speedup vs baseline: 1.5194x; 1.5194x over previous
#include <cuda_runtime.h>
#include <cuda_bf16.h>
#include <math.h>
#include <cstdint>

// ---------------- problem constants ----------------
#define Bb 2
#define Tt 2048
#define Dd 2560
#define Hh 8
#define Gg 4
#define HD 256
#define NQ (Hh*HD)     // 2048
#define NKV (Gg*HD)    // 1024
#define MROWS (Bb*Tt)  // 4096
#define QK_SCALE 0.0625f
#define WINDOW 1024

// ---------------- scratch (static device globals; no allocation) -----------
__device__ float g_q[(size_t)MROWS * NQ];
__device__ float g_k[(size_t)MROWS * NKV];
__device__ float g_v[(size_t)MROWS * NKV];
__device__ float g_ao[(size_t)MROWS * NQ];

// split-precision bf16 operands (16B-aligned for cp.async)
__device__ __align__(256) __nv_bfloat16 g_xhi[(size_t)MROWS * Dd];
__device__ __align__(256) __nv_bfloat16 g_xlo[(size_t)MROWS * Dd];
__device__ __align__(256) __nv_bfloat16 g_aohi[(size_t)MROWS * NQ];
__device__ __align__(256) __nv_bfloat16 g_aolo[(size_t)MROWS * NQ];
__device__ __align__(256) __nv_bfloat16 g_wqhi[(size_t)NQ * Dd];   // [N,K]
__device__ __align__(256) __nv_bfloat16 g_wqlo[(size_t)NQ * Dd];
__device__ __align__(256) __nv_bfloat16 g_wkhi[(size_t)NKV * Dd];
__device__ __align__(256) __nv_bfloat16 g_wklo[(size_t)NKV * Dd];
__device__ __align__(256) __nv_bfloat16 g_wvhi[(size_t)NKV * Dd];
__device__ __align__(256) __nv_bfloat16 g_wvlo[(size_t)NKV * Dd];
__device__ __align__(256) __nv_bfloat16 g_wohi[(size_t)Dd * NQ];
__device__ __align__(256) __nv_bfloat16 g_wolo[(size_t)Dd * NQ];

// ---------------- helpers ----------------------------------------------------
__device__ __forceinline__ uint32_t smem_u32(const void* p) {
    uint32_t a;
    asm("{ .reg .u64 t; cvta.to.shared.u64 t, %1; cvt.u32.u64 %0, t; }"
        : "=r"(a) : "l"(p));
    return a;
}
__device__ __forceinline__ void cp_async16(uint32_t saddr, const void* gaddr) {
    asm volatile("cp.async.cg.shared.global [%0], [%1], 16;"
                 :: "r"(saddr), "l"(gaddr) : "memory");
}
__device__ __forceinline__ void ldmat4(uint32_t* r, uint32_t addr) {
    asm volatile("ldmatrix.sync.aligned.m8n8.x4.shared.b16 {%0,%1,%2,%3}, [%4];"
                 : "=r"(r[0]), "=r"(r[1]), "=r"(r[2]), "=r"(r[3]) : "r"(addr));
}
__device__ __forceinline__ void mma_bf16(float* c, const uint32_t* a, const uint32_t* b) {
    asm volatile(
        "mma.sync.aligned.m16n8k16.row.col.f32.bf16.bf16.f32 "
        "{%0,%1,%2,%3}, {%4,%5,%6,%7}, {%8,%9}, {%0,%1,%2,%3};"
        : "+f"(c[0]), "+f"(c[1]), "+f"(c[2]), "+f"(c[3])
        : "r"(a[0]), "r"(a[1]), "r"(a[2]), "r"(a[3]), "r"(b[0]), "r"(b[1]));
}

// ---------------- split kernels ---------------------------------------------
__global__ __launch_bounds__(256) void split_rows_kernel(
    const float4* __restrict__ in, __nv_bfloat16* __restrict__ hi,
    __nv_bfloat16* __restrict__ lo, int n4)
{
    int i = blockIdx.x * 256 + threadIdx.x;
    if (i >= n4) return;
    float4 v = in[i];
    __nv_bfloat16 h0 = __float2bfloat16_rn(v.x);
    __nv_bfloat16 h1 = __float2bfloat16_rn(v.y);
    __nv_bfloat16 h2 = __float2bfloat16_rn(v.z);
    __nv_bfloat16 h3 = __float2bfloat16_rn(v.w);
    __nv_bfloat16 l0 = __float2bfloat16_rn(v.x - __bfloat162float(h0));
    __nv_bfloat16 l1 = __float2bfloat16_rn(v.y - __bfloat162float(h1));
    __nv_bfloat16 l2 = __float2bfloat16_rn(v.z - __bfloat162float(h2));
    __nv_bfloat16 l3 = __float2bfloat16_rn(v.w - __bfloat162float(h3));
    __nv_bfloat162* hp = (__nv_bfloat162*)(hi + (size_t)i * 4);
    __nv_bfloat162* lp = (__nv_bfloat162*)(lo + (size_t)i * 4);
    hp[0] = __nv_bfloat162(h0, h1); hp[1] = __nv_bfloat162(h2, h3);
    lp[0] = __nv_bfloat162(l0, l1); lp[1] = __nv_bfloat162(l2, l3);
}

// in [K,N] fp32 -> out hi/lo [N,K] bf16
__global__ __launch_bounds__(256) void split_transpose_kernel(
    const float* __restrict__ in, __nv_bfloat16* __restrict__ hi,
    __nv_bfloat16* __restrict__ lo, int K, int N)
{
    __shared__ float t[32][33];
    int n0 = blockIdx.x * 32, k0 = blockIdx.y * 32;
    int tx = threadIdx.x & 31, ty = threadIdx.x >> 5;  // 32 x 8
#pragma unroll
    for (int i = 0; i < 32; i += 8)
        t[ty + i][tx] = in[(size_t)(k0 + ty + i) * N + n0 + tx];
    __syncthreads();
#pragma unroll
    for (int i = 0; i < 32; i += 8) {
        float a = t[tx][ty + i];
        __nv_bfloat16 h = __float2bfloat16_rn(a);
        __nv_bfloat16 l = __float2bfloat16_rn(a - __bfloat162float(h));
        size_t o = (size_t)(n0 + ty + i) * K + k0 + tx;
        hi[o] = h; lo[o] = l;
    }
}

// ---------------- mma.sync split-bf16 GEMM -----------------------------------
// C[M,N] = A[M,K] @ B[N,K]^T with A = Ahi+Alo, B = Bhi+Blo (bf16x3 scheme).
// CTA tile 128x128, BK=32, double-buffered cp.async, 8 warps (4m x 2n).
#define GP 80                 // smem row pitch in BYTES (40 bf16) — conflict-free
#define TILEB (128 * GP)      // 10240 B per 128x32 bf16 tile
#define STAGEB (4 * TILEB)    // Ahi, Alo, Bhi, Blo

__global__ __launch_bounds__(256, 1) void mma_gemm_kernel(
    const __nv_bfloat16* __restrict__ Ahi, const __nv_bfloat16* __restrict__ Alo,
    const __nv_bfloat16* __restrict__ Bhi, const __nv_bfloat16* __restrict__ Blo,
    float* __restrict__ C, int M, int N, int K)
{
    extern __shared__ char smem[];
    uint32_t sb = smem_u32(smem);
    int tid = threadIdx.x, lane = tid & 31, wid = tid >> 5;
    int wm = wid & 3, wn = wid >> 2;          // 4 x 2 warp grid
    int row0 = blockIdx.y * 128, col0 = blockIdx.x * 128;

    const __nv_bfloat16* gsrc[4] = {
        Ahi + (size_t)row0 * K, Alo + (size_t)row0 * K,
        Bhi + (size_t)col0 * K, Blo + (size_t)col0 * K };

    const int NC = K >> 5;

    // per-thread copy coords: 512 16B-chunks per tile, 2 per thread
    int r_ld0 = tid >> 2, c16_0 = tid & 3;
    int r_ld1 = (tid + 256) >> 2, c16_1 = (tid + 256) & 3;

    float acc[2][8][4];
#pragma unroll
    for (int mt = 0; mt < 2; mt++)
#pragma unroll
        for (int nt = 0; nt < 8; nt++)
#pragma unroll
            for (int i = 0; i < 4; i++) acc[mt][nt][i] = 0.f;

    // ldmatrix per-lane offsets
    int grp = lane >> 3, lr = lane & 7;
    uint32_t aoff = (uint32_t)(((grp & 1) * 8 + lr) * GP + (grp >> 1) * 16);
    uint32_t boff = (uint32_t)(((grp >> 1) * 8 + lr) * GP + (grp & 1) * 16);

    auto load_stage = [&](int c) {
        uint32_t st = sb + (uint32_t)(c & 1) * STAGEB;
        int kb = c * 32;
#pragma unroll
        for (int tile = 0; tile < 4; tile++) {
            const __nv_bfloat16* g = gsrc[tile];
            uint32_t tb = st + (uint32_t)tile * TILEB;
            cp_async16(tb + (uint32_t)(r_ld0 * GP + c16_0 * 16),
                       g + (size_t)r_ld0 * K + kb + c16_0 * 8);
            cp_async16(tb + (uint32_t)(r_ld1 * GP + c16_1 * 16),
                       g + (size_t)r_ld1 * K + kb + c16_1 * 8);
        }
        asm volatile("cp.async.commit_group;" ::: "memory");
    };

    load_stage(0);

    for (int c = 0; c < NC; c++) {
        if (c + 1 < NC) {
            load_stage(c + 1);
            asm volatile("cp.async.wait_group 1;" ::: "memory");
        } else {
            asm volatile("cp.async.wait_group 0;" ::: "memory");
        }
        __syncthreads();

        uint32_t st = sb + (uint32_t)(c & 1) * STAGEB;
        uint32_t A0 = st, A1 = st + TILEB, B0 = st + 2 * TILEB, B1 = st + 3 * TILEB;

#pragma unroll
        for (int kk = 0; kk < 2; kk++) {
            uint32_t kbyte = (uint32_t)kk * 32;
            uint32_t ah[2][4], al[2][4], bh[8][2], bl[8][2];
#pragma unroll
            for (int mt = 0; mt < 2; mt++) {
                uint32_t rb = (uint32_t)((wm * 32 + mt * 16) * GP) + aoff + kbyte;
                ldmat4(ah[mt], A0 + rb);
                ldmat4(al[mt], A1 + rb);
            }
#pragma unroll
            for (int nt2 = 0; nt2 < 4; nt2++) {
                uint32_t rb = (uint32_t)((wn * 64 + nt2 * 16) * GP) + boff + kbyte;
                uint32_t r[4];
                ldmat4(r, B0 + rb);
                bh[nt2 * 2][0] = r[0]; bh[nt2 * 2][1] = r[1];
                bh[nt2 * 2 + 1][0] = r[2]; bh[nt2 * 2 + 1][1] = r[3];
                ldmat4(r, B1 + rb);
                bl[nt2 * 2][0] = r[0]; bl[nt2 * 2][1] = r[1];
                bl[nt2 * 2 + 1][0] = r[2]; bl[nt2 * 2 + 1][1] = r[3];
            }
#pragma unroll
            for (int mt = 0; mt < 2; mt++)
#pragma unroll
                for (int nt = 0; nt < 8; nt++) {
                    mma_bf16(acc[mt][nt], ah[mt], bh[nt]);
                    mma_bf16(acc[mt][nt], ah[mt], bl[nt]);
                    mma_bf16(acc[mt][nt], al[mt], bh[nt]);
                }
        }
        __syncthreads();
    }

    // epilogue
#pragma unroll
    for (int mt = 0; mt < 2; mt++) {
        int rg0 = row0 + wm * 32 + mt * 16 + (lane >> 2);
#pragma unroll
        for (int nt = 0; nt < 8; nt++) {
            int cg = col0 + wn * 64 + nt * 8 + (lane & 3) * 2;
            *(float2*)(C + (size_t)rg0 * N + cg) =
                make_float2(acc[mt][nt][0], acc[mt][nt][1]);
            *(float2*)(C + (size_t)(rg0 + 8) * N + cg) =
                make_float2(acc[mt][nt][2], acc[mt][nt][3]);
        }
    }
}

// ---------------- Gemma RMSNorm over contiguous 256-float rows -------------
__global__ __launch_bounds__(256) void rmsnorm_kernel(
    float* __restrict__ buf, const float* __restrict__ scale)
{
    int row = blockIdx.x;
    int d = threadIdx.x;
    float* p = buf + (size_t)row * HD;
    float x = p[d];
    float v = x * x;
#pragma unroll
    for (int o = 16; o > 0; o >>= 1) v += __shfl_xor_sync(0xffffffffu, v, o);
    __shared__ float ws[8];
    __shared__ float stot;
    if ((d & 31) == 0) ws[d >> 5] = v;
    __syncthreads();
    if (d == 0) {
        float s = 0.f;
#pragma unroll
        for (int i = 0; i < 8; i++) s += ws[i];
        stot = s;
    }
    __syncthreads();
    float r = rsqrtf(stot * (1.f / HD) + 1e-6f);
    p[d] = x * r * (1.f + scale[d]);
}

// ---------------- sliding-window flash attention (fp32) --------------------
#define AQT 32
#define QPAD 257
#define SPAD 33

__global__ __launch_bounds__(256) void attn_kernel()
{
    extern __shared__ float sm[];
    float* Qs = sm;
    float* Ks = Qs + AQT * QPAD;
    float* Vs = Ks + AQT * QPAD;
    float* Ss = Vs + AQT * QPAD;
    float* lrow = Ss + AQT * SPAD;
    float* arow = lrow + AQT;

    int tid = threadIdx.x;
    int qt = blockIdx.x;
    int h  = blockIdx.y;
    int b  = blockIdx.z;
    int t0 = qt * AQT;
    int kvh = h & (Gg - 1);

    for (int idx = tid; idx < AQT * HD; idx += 256) {
        int qi = idx >> 8, d = idx & 255;
        Qs[qi * QPAD + d] =
            g_q[((size_t)(b * Tt + t0 + qi)) * NQ + h * HD + d] * QK_SCALE;
    }

    int qi_o = tid >> 3;
    int dseg = tid & 7;
    float o[32];
#pragma unroll
    for (int j = 0; j < 32; j++) o[j] = 0.f;

    float mreg = -1e30f, lreg = 0.f;

    int kb0 = max(0, t0 - (WINDOW - 1)) >> 5;
    int kb1 = (t0 + AQT - 1) >> 5;

    for (int kb = kb0; kb <= kb1; kb++) {
        int s0 = kb * AQT;
        __syncthreads();

        for (int idx = tid; idx < AQT * HD; idx += 256) {
            int ki = idx >> 8, d = idx & 255;
            size_t gr = ((size_t)(b * Tt + s0 + ki)) * NKV + kvh * HD + d;
            Ks[ki * QPAD + d] = g_k[gr];
            Vs[ki * QPAD + d] = g_v[gr];
        }
        __syncthreads();

        int q2 = (tid >> 4) << 1;
        int k2 = (tid & 15) << 1;
        float s00 = 0.f, s01 = 0.f, s10 = 0.f, s11 = 0.f;
        const float* q0p = Qs + q2 * QPAD;
        const float* q1p = q0p + QPAD;
        const float* k0p = Ks + k2 * QPAD;
        const float* k1p = k0p + QPAD;
#pragma unroll 4
        for (int d = 0; d < HD; d++) {
            float q0v = q0p[d], q1v = q1p[d];
            float k0v = k0p[d], k1v = k1p[d];
            s00 += q0v * k0v; s01 += q0v * k1v;
            s10 += q1v * k0v; s11 += q1v * k1v;
        }
        {
            int tq0 = t0 + q2, tq1 = tq0 + 1;
            int kk0 = s0 + k2, kk1 = kk0 + 1;
            Ss[q2 * SPAD + k2]           = (kk0 > tq0 || kk0 < tq0 - (WINDOW - 1)) ? -1e30f : s00;
            Ss[q2 * SPAD + k2 + 1]       = (kk1 > tq0 || kk1 < tq0 - (WINDOW - 1)) ? -1e30f : s01;
            Ss[(q2 + 1) * SPAD + k2]     = (kk0 > tq1 || kk0 < tq1 - (WINDOW - 1)) ? -1e30f : s10;
            Ss[(q2 + 1) * SPAD + k2 + 1] = (kk1 > tq1 || kk1 < tq1 - (WINDOW - 1)) ? -1e30f : s11;
        }
        __syncthreads();

        if (tid < 32) {
            float* srow = Ss + tid * SPAD;
            float mnew = mreg;
#pragma unroll
            for (int j = 0; j < 32; j++) mnew = fmaxf(mnew, srow[j]);
            float alpha = __expf(mreg - mnew);
            float sum = 0.f;
#pragma unroll
            for (int j = 0; j < 32; j++) {
                float s = srow[j];
                float p = __expf(s - mnew);
                if (s < -1e29f) p = 0.f;
                srow[j] = p;
                sum += p;
            }
            lreg = lreg * alpha + sum;
            mreg = mnew;
            arow[tid] = alpha;
            lrow[tid] = lreg;
        }
        __syncthreads();

        float al = arow[qi_o];
#pragma unroll
        for (int j = 0; j < 32; j++) o[j] *= al;
        const float* prow = Ss + qi_o * SPAD;
#pragma unroll 8
        for (int k = 0; k < 32; k++) {
            float p = prow[k];
            const float* vrow = Vs + k * QPAD + dseg;
#pragma unroll
            for (int j = 0; j < 32; j++) o[j] += p * vrow[j * 8];
        }
    }
    __syncthreads();

    float invl = 1.f / lrow[qi_o];
    float* op = g_ao + ((size_t)(b * Tt + t0 + qi_o)) * NQ + h * HD + dseg;
#pragma unroll
    for (int j = 0; j < 32; j++) op[j * 8] = o[j] * invl;
}

// ---------------- launch ----------------------------------------------------
extern "C" void kernel_launch(void* const* d_in, const int* in_sizes, int n_in,
                              void* d_out, int out_size)
{
    const float* x   = (const float*)d_in[0];
    const float* Wq  = (const float*)d_in[1];
    const float* Wk  = (const float*)d_in[2];
    const float* Wv  = (const float*)d_in[3];
    const float* Wo  = (const float*)d_in[4];
    const float* qsc = (const float*)d_in[5];
    const float* ksc = (const float*)d_in[6];
    float* out = (float*)d_out;

    void *pq, *pk, *pv, *pao;
    void *pxh, *pxl, *paoh, *paol;
    void *pwqh, *pwql, *pwkh, *pwkl, *pwvh, *pwvl, *pwoh, *pwol;
    cudaGetSymbolAddress(&pq, g_q);   cudaGetSymbolAddress(&pk, g_k);
    cudaGetSymbolAddress(&pv, g_v);   cudaGetSymbolAddress(&pao, g_ao);
    cudaGetSymbolAddress(&pxh, g_xhi);  cudaGetSymbolAddress(&pxl, g_xlo);
    cudaGetSymbolAddress(&paoh, g_aohi); cudaGetSymbolAddress(&paol, g_aolo);
    cudaGetSymbolAddress(&pwqh, g_wqhi); cudaGetSymbolAddress(&pwql, g_wqlo);
    cudaGetSymbolAddress(&pwkh, g_wkhi); cudaGetSymbolAddress(&pwkl, g_wklo);
    cudaGetSymbolAddress(&pwvh, g_wvhi); cudaGetSymbolAddress(&pwvl, g_wvlo);
    cudaGetSymbolAddress(&pwoh, g_wohi); cudaGetSymbolAddress(&pwol, g_wolo);

    float* dq  = (float*)pq;  float* dk = (float*)pk;
    float* dv  = (float*)pv;  float* dao = (float*)pao;
    __nv_bfloat16* xh = (__nv_bfloat16*)pxh;  __nv_bfloat16* xl = (__nv_bfloat16*)pxl;
    __nv_bfloat16* aoh = (__nv_bfloat16*)paoh; __nv_bfloat16* aol = (__nv_bfloat16*)paol;
    __nv_bfloat16* wqh = (__nv_bfloat16*)pwqh; __nv_bfloat16* wql = (__nv_bfloat16*)pwql;
    __nv_bfloat16* wkh = (__nv_bfloat16*)pwkh; __nv_bfloat16* wkl = (__nv_bfloat16*)pwkl;
    __nv_bfloat16* wvh = (__nv_bfloat16*)pwvh; __nv_bfloat16* wvl = (__nv_bfloat16*)pwvl;
    __nv_bfloat16* woh = (__nv_bfloat16*)pwoh; __nv_bfloat16* wol = (__nv_bfloat16*)pwol;

    size_t gemm_smem = 2 * STAGEB;  // 81920
    cudaFuncSetAttribute(mma_gemm_kernel,
                         cudaFuncAttributeMaxDynamicSharedMemorySize, (int)gemm_smem);

    // ---- splits for Q/K/V projections ----
    {
        int n4 = (MROWS * Dd) / 4;
        split_rows_kernel<<<(n4 + 255) / 256, 256>>>((const float4*)x, xh, xl, n4);
        split_transpose_kernel<<<dim3(NQ / 32, Dd / 32), 256>>>(Wq, wqh, wql, Dd, NQ);
        split_transpose_kernel<<<dim3(NKV / 32, Dd / 32), 256>>>(Wk, wkh, wkl, Dd, NKV);
        split_transpose_kernel<<<dim3(NKV / 32, Dd / 32), 256>>>(Wv, wvh, wvl, Dd, NKV);
    }

    // ---- projections (tensor cores) ----
    {
        dim3 blk(256);
        mma_gemm_kernel<<<dim3(NQ / 128,  MROWS / 128), blk, gemm_smem>>>(
            xh, xl, wqh, wql, dq, MROWS, NQ, Dd);
        mma_gemm_kernel<<<dim3(NKV / 128, MROWS / 128), blk, gemm_smem>>>(
            xh, xl, wkh, wkl, dk, MROWS, NKV, Dd);
        mma_gemm_kernel<<<dim3(NKV / 128, MROWS / 128), blk, gemm_smem>>>(
            xh, xl, wvh, wvl, dv, MROWS, NKV, Dd);
    }

    // ---- qk-norm ----
    rmsnorm_kernel<<<MROWS * Hh, 256>>>(dq, qsc);
    rmsnorm_kernel<<<MROWS * Gg, 256>>>(dk, ksc);

    // ---- attention ----
    {
        size_t smem = (size_t)(3 * AQT * QPAD + AQT * SPAD + 2 * AQT) * sizeof(float);
        cudaFuncSetAttribute(attn_kernel,
                             cudaFuncAttributeMaxDynamicSharedMemorySize, (int)smem);
        dim3 grid(Tt / AQT, Hh, Bb);
        attn_kernel<<<grid, 256, smem>>>();
    }

    // ---- output projection ----
    {
        int n4 = (MROWS * NQ) / 4;
        split_rows_kernel<<<(n4 + 255) / 256, 256>>>((const float4*)dao, aoh, aol, n4);
        split_transpose_kernel<<<dim3(Dd / 32, NQ / 32), 256>>>(Wo, woh, wol, NQ, Dd);
        mma_gemm_kernel<<<dim3(Dd / 128, MROWS / 128), 256, gemm_smem>>>(
            aoh, aol, woh, wol, out, MROWS, Dd, NQ);
    }
}

// round 4
// speedup vs baseline: 1.6449x; 1.0826x over previous
#include <cuda_runtime.h>
#include <cuda_bf16.h>
#include <math.h>
#include <cstdint>

// ---------------- problem constants ----------------
#define Bb 2
#define Tt 2048
#define Dd 2560
#define Hh 8
#define Gg 4
#define HD 256
#define NQ (Hh*HD)     // 2048
#define NKV (Gg*HD)    // 1024
#define MROWS (Bb*Tt)  // 4096
#define QK_SCALE 0.0625f
#define WINDOW 1024

// ---------------- scratch (static device globals; no allocation) -----------
__device__ float g_q[(size_t)MROWS * NQ];
__device__ float g_k[(size_t)MROWS * NKV];
__device__ float g_v[(size_t)MROWS * NKV];
__device__ float g_ao[(size_t)MROWS * NQ];

// split-precision bf16 operands (16B-aligned for cp.async)
__device__ __align__(256) __nv_bfloat16 g_xhi[(size_t)MROWS * Dd];
__device__ __align__(256) __nv_bfloat16 g_xlo[(size_t)MROWS * Dd];
__device__ __align__(256) __nv_bfloat16 g_aohi[(size_t)MROWS * NQ];
__device__ __align__(256) __nv_bfloat16 g_aolo[(size_t)MROWS * NQ];
__device__ __align__(256) __nv_bfloat16 g_wqhi[(size_t)NQ * Dd];   // [N,K]
__device__ __align__(256) __nv_bfloat16 g_wqlo[(size_t)NQ * Dd];
__device__ __align__(256) __nv_bfloat16 g_wkhi[(size_t)NKV * Dd];
__device__ __align__(256) __nv_bfloat16 g_wklo[(size_t)NKV * Dd];
__device__ __align__(256) __nv_bfloat16 g_wvhi[(size_t)NKV * Dd];
__device__ __align__(256) __nv_bfloat16 g_wvlo[(size_t)NKV * Dd];
__device__ __align__(256) __nv_bfloat16 g_wohi[(size_t)Dd * NQ];
__device__ __align__(256) __nv_bfloat16 g_wolo[(size_t)Dd * NQ];

// ---------------- helpers ----------------------------------------------------
__device__ __forceinline__ uint32_t smem_u32(const void* p) {
    uint32_t a;
    asm("{ .reg .u64 t; cvta.to.shared.u64 t, %1; cvt.u32.u64 %0, t; }"
        : "=r"(a) : "l"(p));
    return a;
}
__device__ __forceinline__ void cp_async16(uint32_t saddr, const void* gaddr) {
    asm volatile("cp.async.cg.shared.global [%0], [%1], 16;"
                 :: "r"(saddr), "l"(gaddr) : "memory");
}
__device__ __forceinline__ void ldmat4(uint32_t* r, uint32_t addr) {
    asm volatile("ldmatrix.sync.aligned.m8n8.x4.shared.b16 {%0,%1,%2,%3}, [%4];"
                 : "=r"(r[0]), "=r"(r[1]), "=r"(r[2]), "=r"(r[3]) : "r"(addr));
}
__device__ __forceinline__ void mma_bf16(float* c, const uint32_t* a, const uint32_t* b) {
    asm volatile(
        "mma.sync.aligned.m16n8k16.row.col.f32.bf16.bf16.f32 "
        "{%0,%1,%2,%3}, {%4,%5,%6,%7}, {%8,%9}, {%0,%1,%2,%3};"
        : "+f"(c[0]), "+f"(c[1]), "+f"(c[2]), "+f"(c[3])
        : "r"(a[0]), "r"(a[1]), "r"(a[2]), "r"(a[3]), "r"(b[0]), "r"(b[1]));
}

// ---------------- split kernels ---------------------------------------------
__global__ __launch_bounds__(256) void split_rows_kernel(
    const float4* __restrict__ in, __nv_bfloat16* __restrict__ hi,
    __nv_bfloat16* __restrict__ lo, int n4)
{
    int i = blockIdx.x * 256 + threadIdx.x;
    if (i >= n4) return;
    float4 v = in[i];
    __nv_bfloat16 h0 = __float2bfloat16_rn(v.x);
    __nv_bfloat16 h1 = __float2bfloat16_rn(v.y);
    __nv_bfloat16 h2 = __float2bfloat16_rn(v.z);
    __nv_bfloat16 h3 = __float2bfloat16_rn(v.w);
    __nv_bfloat16 l0 = __float2bfloat16_rn(v.x - __bfloat162float(h0));
    __nv_bfloat16 l1 = __float2bfloat16_rn(v.y - __bfloat162float(h1));
    __nv_bfloat16 l2 = __float2bfloat16_rn(v.z - __bfloat162float(h2));
    __nv_bfloat16 l3 = __float2bfloat16_rn(v.w - __bfloat162float(h3));
    __nv_bfloat162* hp = (__nv_bfloat162*)(hi + (size_t)i * 4);
    __nv_bfloat162* lp = (__nv_bfloat162*)(lo + (size_t)i * 4);
    hp[0] = __nv_bfloat162(h0, h1); hp[1] = __nv_bfloat162(h2, h3);
    lp[0] = __nv_bfloat162(l0, l1); lp[1] = __nv_bfloat162(l2, l3);
}

// in [K,N] fp32 -> out hi/lo [N,K] bf16
__global__ __launch_bounds__(256) void split_transpose_kernel(
    const float* __restrict__ in, __nv_bfloat16* __restrict__ hi,
    __nv_bfloat16* __restrict__ lo, int K, int N)
{
    __shared__ float t[32][33];
    int n0 = blockIdx.x * 32, k0 = blockIdx.y * 32;
    int tx = threadIdx.x & 31, ty = threadIdx.x >> 5;  // 32 x 8
#pragma unroll
    for (int i = 0; i < 32; i += 8)
        t[ty + i][tx] = in[(size_t)(k0 + ty + i) * N + n0 + tx];
    __syncthreads();
#pragma unroll
    for (int i = 0; i < 32; i += 8) {
        float a = t[tx][ty + i];
        __nv_bfloat16 h = __float2bfloat16_rn(a);
        __nv_bfloat16 l = __float2bfloat16_rn(a - __bfloat162float(h));
        size_t o = (size_t)(n0 + ty + i) * K + k0 + tx;
        hi[o] = h; lo[o] = l;
    }
}

// ---------------- mma.sync split-bf16 GEMM -----------------------------------
// C[M,N] = A[M,K] @ B[N,K]^T with A = Ahi+Alo, B = Bhi+Blo (bf16x3 scheme).
// CTA tile 128x128, BK=32, double-buffered cp.async, 8 warps (4m x 2n),
// 2 CTAs / SM for latency hiding.
#define GP 80                 // smem row pitch in BYTES (40 bf16) — conflict-free
#define TILEB (128 * GP)      // 10240 B per 128x32 bf16 tile
#define STAGEB (4 * TILEB)    // Ahi, Alo, Bhi, Blo

__global__ __launch_bounds__(256, 2) void mma_gemm_kernel(
    const __nv_bfloat16* __restrict__ Ahi, const __nv_bfloat16* __restrict__ Alo,
    const __nv_bfloat16* __restrict__ Bhi, const __nv_bfloat16* __restrict__ Blo,
    float* __restrict__ C, int M, int N, int K)
{
    extern __shared__ char smem[];
    uint32_t sb = smem_u32(smem);
    int tid = threadIdx.x, lane = tid & 31, wid = tid >> 5;
    int wm = wid & 3, wn = wid >> 2;          // 4 x 2 warp grid
    int row0 = blockIdx.y * 128, col0 = blockIdx.x * 128;

    const __nv_bfloat16* gsrc[4] = {
        Ahi + (size_t)row0 * K, Alo + (size_t)row0 * K,
        Bhi + (size_t)col0 * K, Blo + (size_t)col0 * K };

    const int NC = K >> 5;

    // per-thread copy coords: 512 16B-chunks per tile, 2 per thread
    int r_ld0 = tid >> 2, c16_0 = tid & 3;
    int r_ld1 = (tid + 256) >> 2, c16_1 = (tid + 256) & 3;

    float acc[2][8][4];
#pragma unroll
    for (int mt = 0; mt < 2; mt++)
#pragma unroll
        for (int nt = 0; nt < 8; nt++)
#pragma unroll
            for (int i = 0; i < 4; i++) acc[mt][nt][i] = 0.f;

    // ldmatrix per-lane offsets
    int grp = lane >> 3, lr = lane & 7;
    uint32_t aoff = (uint32_t)(((grp & 1) * 8 + lr) * GP + (grp >> 1) * 16);
    uint32_t boff = (uint32_t)(((grp >> 1) * 8 + lr) * GP + (grp & 1) * 16);

    auto load_stage = [&](int c) {
        uint32_t st = sb + (uint32_t)(c & 1) * STAGEB;
        int kb = c * 32;
#pragma unroll
        for (int tile = 0; tile < 4; tile++) {
            const __nv_bfloat16* g = gsrc[tile];
            uint32_t tb = st + (uint32_t)tile * TILEB;
            cp_async16(tb + (uint32_t)(r_ld0 * GP + c16_0 * 16),
                       g + (size_t)r_ld0 * K + kb + c16_0 * 8);
            cp_async16(tb + (uint32_t)(r_ld1 * GP + c16_1 * 16),
                       g + (size_t)r_ld1 * K + kb + c16_1 * 8);
        }
        asm volatile("cp.async.commit_group;" ::: "memory");
    };

    load_stage(0);

    for (int c = 0; c < NC; c++) {
        if (c + 1 < NC) {
            load_stage(c + 1);
            asm volatile("cp.async.wait_group 1;" ::: "memory");
        } else {
            asm volatile("cp.async.wait_group 0;" ::: "memory");
        }
        __syncthreads();

        uint32_t st = sb + (uint32_t)(c & 1) * STAGEB;
        uint32_t A0 = st, A1 = st + TILEB, B0 = st + 2 * TILEB, B1 = st + 3 * TILEB;

#pragma unroll
        for (int kk = 0; kk < 2; kk++) {
            uint32_t kbyte = (uint32_t)kk * 32;
            uint32_t ah[2][4], al[2][4];
#pragma unroll
            for (int mt = 0; mt < 2; mt++) {
                uint32_t rb = (uint32_t)((wm * 32 + mt * 16) * GP) + aoff + kbyte;
                ldmat4(ah[mt], A0 + rb);
                ldmat4(al[mt], A1 + rb);
            }
            // B fragments in two halves of 4 n-tiles each (register pressure)
#pragma unroll
            for (int nh = 0; nh < 2; nh++) {
                uint32_t bh[4][2], bl[4][2];
#pragma unroll
                for (int nt2 = 0; nt2 < 2; nt2++) {
                    uint32_t rb = (uint32_t)((wn * 64 + nh * 32 + nt2 * 16) * GP)
                                + boff + kbyte;
                    uint32_t r[4];
                    ldmat4(r, B0 + rb);
                    bh[nt2 * 2][0] = r[0]; bh[nt2 * 2][1] = r[1];
                    bh[nt2 * 2 + 1][0] = r[2]; bh[nt2 * 2 + 1][1] = r[3];
                    ldmat4(r, B1 + rb);
                    bl[nt2 * 2][0] = r[0]; bl[nt2 * 2][1] = r[1];
                    bl[nt2 * 2 + 1][0] = r[2]; bl[nt2 * 2 + 1][1] = r[3];
                }
#pragma unroll
                for (int mt = 0; mt < 2; mt++)
#pragma unroll
                    for (int nt = 0; nt < 4; nt++) {
                        float* a = acc[mt][nh * 4 + nt];
                        mma_bf16(a, ah[mt], bh[nt]);
                        mma_bf16(a, ah[mt], bl[nt]);
                        mma_bf16(a, al[mt], bh[nt]);
                    }
            }
        }
        __syncthreads();
    }

    // epilogue
#pragma unroll
    for (int mt = 0; mt < 2; mt++) {
        int rg0 = row0 + wm * 32 + mt * 16 + (lane >> 2);
#pragma unroll
        for (int nt = 0; nt < 8; nt++) {
            int cg = col0 + wn * 64 + nt * 8 + (lane & 3) * 2;
            *(float2*)(C + (size_t)rg0 * N + cg) =
                make_float2(acc[mt][nt][0], acc[mt][nt][1]);
            *(float2*)(C + (size_t)(rg0 + 8) * N + cg) =
                make_float2(acc[mt][nt][2], acc[mt][nt][3]);
        }
    }
}

// ---------------- Gemma RMSNorm over contiguous 256-float rows -------------
__global__ __launch_bounds__(256) void rmsnorm_kernel(
    float* __restrict__ buf, const float* __restrict__ scale)
{
    int row = blockIdx.x;
    int d = threadIdx.x;
    float* p = buf + (size_t)row * HD;
    float x = p[d];
    float v = x * x;
#pragma unroll
    for (int o = 16; o > 0; o >>= 1) v += __shfl_xor_sync(0xffffffffu, v, o);
    __shared__ float ws[8];
    __shared__ float stot;
    if ((d & 31) == 0) ws[d >> 5] = v;
    __syncthreads();
    if (d == 0) {
        float s = 0.f;
#pragma unroll
        for (int i = 0; i < 8; i++) s += ws[i];
        stot = s;
    }
    __syncthreads();
    float r = rsqrtf(stot * (1.f / HD) + 1e-6f);
    p[d] = x * r * (1.f + scale[d]);
}

// ---------------- sliding-window flash attention (fp32) --------------------
#define AQT 32
#define QPAD 257   // Q/K pitch (scalar access)
#define VPAD 260   // V pitch: 16B-aligned rows for LDS.128
#define SPAD 33

__global__ __launch_bounds__(256) void attn_kernel()
{
    extern __shared__ float sm[];
    float* Qs = sm;                     // [32][257]
    float* Ks = Qs + AQT * QPAD;        // [32][257]
    float* Vs = Ks + AQT * QPAD;        // [32][260]
    float* Ss = Vs + AQT * VPAD;        // [32][33]
    float* lrow = Ss + AQT * SPAD;
    float* arow = lrow + AQT;

    int tid = threadIdx.x;
    int qt = blockIdx.x;
    int h  = blockIdx.y;
    int b  = blockIdx.z;
    int t0 = qt * AQT;
    int kvh = h & (Gg - 1);

    for (int idx = tid; idx < AQT * HD; idx += 256) {
        int qi = idx >> 8, d = idx & 255;
        Qs[qi * QPAD + d] =
            g_q[((size_t)(b * Tt + t0 + qi)) * NQ + h * HD + d] * QK_SCALE;
    }

    int qi_o = tid >> 3;   // output query row
    int dseg = tid & 7;    // owns d = dseg*4 + 32*j (float4 chunks)
    float4 o4[8];
#pragma unroll
    for (int j = 0; j < 8; j++) o4[j] = make_float4(0.f, 0.f, 0.f, 0.f);

    float mreg = -1e30f, lreg = 0.f;

    int kb0 = max(0, t0 - (WINDOW - 1)) >> 5;
    int kb1 = (t0 + AQT - 1) >> 5;

    for (int kb = kb0; kb <= kb1; kb++) {
        int s0 = kb * AQT;
        __syncthreads();

        // K scalar fill (coalesced), V vectorized fill
        for (int idx = tid; idx < AQT * HD; idx += 256) {
            int ki = idx >> 8, d = idx & 255;
            Ks[ki * QPAD + d] =
                g_k[((size_t)(b * Tt + s0 + ki)) * NKV + kvh * HD + d];
        }
        for (int idx = tid; idx < AQT * (HD / 4); idx += 256) {
            int ki = idx >> 6, dc = idx & 63;
            float4 vv = *(const float4*)(
                g_v + ((size_t)(b * Tt + s0 + ki)) * NKV + kvh * HD + dc * 4);
            *(float4*)(Vs + ki * VPAD + dc * 4) = vv;
        }
        __syncthreads();

        // scores: 2x2 micro-tile per thread
        int q2 = (tid >> 4) << 1;
        int k2 = (tid & 15) << 1;
        float s00 = 0.f, s01 = 0.f, s10 = 0.f, s11 = 0.f;
        const float* q0p = Qs + q2 * QPAD;
        const float* q1p = q0p + QPAD;
        const float* k0p = Ks + k2 * QPAD;
        const float* k1p = k0p + QPAD;
#pragma unroll 4
        for (int d = 0; d < HD; d++) {
            float q0v = q0p[d], q1v = q1p[d];
            float k0v = k0p[d], k1v = k1p[d];
            s00 += q0v * k0v; s01 += q0v * k1v;
            s10 += q1v * k0v; s11 += q1v * k1v;
        }
        {
            int tq0 = t0 + q2, tq1 = tq0 + 1;
            int kk0 = s0 + k2, kk1 = kk0 + 1;
            Ss[q2 * SPAD + k2]           = (kk0 > tq0 || kk0 < tq0 - (WINDOW - 1)) ? -1e30f : s00;
            Ss[q2 * SPAD + k2 + 1]       = (kk1 > tq0 || kk1 < tq0 - (WINDOW - 1)) ? -1e30f : s01;
            Ss[(q2 + 1) * SPAD + k2]     = (kk0 > tq1 || kk0 < tq1 - (WINDOW - 1)) ? -1e30f : s10;
            Ss[(q2 + 1) * SPAD + k2 + 1] = (kk1 > tq1 || kk1 < tq1 - (WINDOW - 1)) ? -1e30f : s11;
        }
        __syncthreads();

        // online softmax (one thread per query row)
        if (tid < 32) {
            float* srow = Ss + tid * SPAD;
            float mnew = mreg;
#pragma unroll
            for (int j = 0; j < 32; j++) mnew = fmaxf(mnew, srow[j]);
            float alpha = __expf(mreg - mnew);
            float sum = 0.f;
#pragma unroll
            for (int j = 0; j < 32; j++) {
                float s = srow[j];
                float p = __expf(s - mnew);
                if (s < -1e29f) p = 0.f;
                srow[j] = p;
                sum += p;
            }
            lreg = lreg * alpha + sum;
            mreg = mnew;
            arow[tid] = alpha;
            lrow[tid] = lreg;
        }
        __syncthreads();

        // O = O*alpha + P @ V  (vectorized over d)
        float al = arow[qi_o];
#pragma unroll
        for (int j = 0; j < 8; j++) {
            o4[j].x *= al; o4[j].y *= al; o4[j].z *= al; o4[j].w *= al;
        }
        const float* prow = Ss + qi_o * SPAD;
#pragma unroll 4
        for (int k = 0; k < 32; k++) {
            float p = prow[k];
            const float4* vrow = (const float4*)(Vs + k * VPAD) + dseg;
#pragma unroll
            for (int j = 0; j < 8; j++) {
                float4 vv = vrow[j * 8];
                o4[j].x += p * vv.x; o4[j].y += p * vv.y;
                o4[j].z += p * vv.z; o4[j].w += p * vv.w;
            }
        }
    }
    __syncthreads();

    float invl = 1.f / lrow[qi_o];
    float* op = g_ao + ((size_t)(b * Tt + t0 + qi_o)) * NQ + h * HD + dseg * 4;
#pragma unroll
    for (int j = 0; j < 8; j++) {
        float4 v = make_float4(o4[j].x * invl, o4[j].y * invl,
                               o4[j].z * invl, o4[j].w * invl);
        *(float4*)(op + j * 32) = v;
    }
}

// ---------------- launch ----------------------------------------------------
extern "C" void kernel_launch(void* const* d_in, const int* in_sizes, int n_in,
                              void* d_out, int out_size)
{
    const float* x   = (const float*)d_in[0];
    const float* Wq  = (const float*)d_in[1];
    const float* Wk  = (const float*)d_in[2];
    const float* Wv  = (const float*)d_in[3];
    const float* Wo  = (const float*)d_in[4];
    const float* qsc = (const float*)d_in[5];
    const float* ksc = (const float*)d_in[6];
    float* out = (float*)d_out;

    void *pq, *pk, *pv, *pao;
    void *pxh, *pxl, *paoh, *paol;
    void *pwqh, *pwql, *pwkh, *pwkl, *pwvh, *pwvl, *pwoh, *pwol;
    cudaGetSymbolAddress(&pq, g_q);   cudaGetSymbolAddress(&pk, g_k);
    cudaGetSymbolAddress(&pv, g_v);   cudaGetSymbolAddress(&pao, g_ao);
    cudaGetSymbolAddress(&pxh, g_xhi);  cudaGetSymbolAddress(&pxl, g_xlo);
    cudaGetSymbolAddress(&paoh, g_aohi); cudaGetSymbolAddress(&paol, g_aolo);
    cudaGetSymbolAddress(&pwqh, g_wqhi); cudaGetSymbolAddress(&pwql, g_wqlo);
    cudaGetSymbolAddress(&pwkh, g_wkhi); cudaGetSymbolAddress(&pwkl, g_wklo);
    cudaGetSymbolAddress(&pwvh, g_wvhi); cudaGetSymbolAddress(&pwvl, g_wvlo);
    cudaGetSymbolAddress(&pwoh, g_wohi); cudaGetSymbolAddress(&pwol, g_wolo);

    float* dq  = (float*)pq;  float* dk = (float*)pk;
    float* dv  = (float*)pv;  float* dao = (float*)pao;
    __nv_bfloat16* xh = (__nv_bfloat16*)pxh;  __nv_bfloat16* xl = (__nv_bfloat16*)pxl;
    __nv_bfloat16* aoh = (__nv_bfloat16*)paoh; __nv_bfloat16* aol = (__nv_bfloat16*)paol;
    __nv_bfloat16* wqh = (__nv_bfloat16*)pwqh; __nv_bfloat16* wql = (__nv_bfloat16*)pwql;
    __nv_bfloat16* wkh = (__nv_bfloat16*)pwkh; __nv_bfloat16* wkl = (__nv_bfloat16*)pwkl;
    __nv_bfloat16* wvh = (__nv_bfloat16*)pwvh; __nv_bfloat16* wvl = (__nv_bfloat16*)pwvl;
    __nv_bfloat16* woh = (__nv_bfloat16*)pwoh; __nv_bfloat16* wol = (__nv_bfloat16*)pwol;

    size_t gemm_smem = 2 * STAGEB;  // 81920
    cudaFuncSetAttribute(mma_gemm_kernel,
                         cudaFuncAttributeMaxDynamicSharedMemorySize, (int)gemm_smem);

    // ---- splits for Q/K/V projections ----
    {
        int n4 = (MROWS * Dd) / 4;
        split_rows_kernel<<<(n4 + 255) / 256, 256>>>((const float4*)x, xh, xl, n4);
        split_transpose_kernel<<<dim3(NQ / 32, Dd / 32), 256>>>(Wq, wqh, wql, Dd, NQ);
        split_transpose_kernel<<<dim3(NKV / 32, Dd / 32), 256>>>(Wk, wkh, wkl, Dd, NKV);
        split_transpose_kernel<<<dim3(NKV / 32, Dd / 32), 256>>>(Wv, wvh, wvl, Dd, NKV);
    }

    // ---- projections (tensor cores) ----
    {
        dim3 blk(256);
        mma_gemm_kernel<<<dim3(NQ / 128,  MROWS / 128), blk, gemm_smem>>>(
            xh, xl, wqh, wql, dq, MROWS, NQ, Dd);
        mma_gemm_kernel<<<dim3(NKV / 128, MROWS / 128), blk, gemm_smem>>>(
            xh, xl, wkh, wkl, dk, MROWS, NKV, Dd);
        mma_gemm_kernel<<<dim3(NKV / 128, MROWS / 128), blk, gemm_smem>>>(
            xh, xl, wvh, wvl, dv, MROWS, NKV, Dd);
    }

    // ---- qk-norm ----
    rmsnorm_kernel<<<MROWS * Hh, 256>>>(dq, qsc);
    rmsnorm_kernel<<<MROWS * Gg, 256>>>(dk, ksc);

    // ---- attention ----
    {
        size_t smem = (size_t)(2 * AQT * QPAD + AQT * VPAD + AQT * SPAD + 2 * AQT)
                      * sizeof(float);
        cudaFuncSetAttribute(attn_kernel,
                             cudaFuncAttributeMaxDynamicSharedMemorySize, (int)smem);
        dim3 grid(Tt / AQT, Hh, Bb);
        attn_kernel<<<grid, 256, smem>>>();
    }

    // ---- output projection ----
    {
        int n4 = (MROWS * NQ) / 4;
        split_rows_kernel<<<(n4 + 255) / 256, 256>>>((const float4*)dao, aoh, aol, n4);
        split_transpose_kernel<<<dim3(Dd / 32, NQ / 32), 256>>>(Wo, woh, wol, NQ, Dd);
        mma_gemm_kernel<<<dim3(Dd / 128, MROWS / 128), 256, gemm_smem>>>(
            aoh, aol, woh, wol, out, MROWS, Dd, NQ);
    }
}